// round 8
// baseline (speedup 1.0000x reference)
#include <cuda_runtime.h>
#include <math.h>

#define Bn   65536
#define Tn   5
#define BT   (Bn*Tn)
#define EPSf 1e-12f

typedef unsigned long long u64;

__device__ float g_x[BT * 64];
__device__ float g_ys[2][BT * 64];
__device__ int   g_cnt[5];
__device__ int   g_cursor[5];
__device__ int   g_perm[Bn];

extern __shared__ float smem[];

__device__ __forceinline__ u64 splat2(float x) {
    u64 r; asm("mov.b64 %0, {%1, %1};" : "=l"(r) : "f"(x)); return r;
}
__device__ __forceinline__ void ffma2(u64& d, u64 a, u64 b) {
    asm("fma.rn.f32x2 %0, %1, %2, %0;" : "+l"(d) : "l"(a), "l"(b));
}
__device__ __forceinline__ void lds_v2u64(u64& a, u64& b, unsigned addr) {
    asm volatile("ld.shared.v2.u64 {%0, %1}, [%2];" : "=l"(a), "=l"(b) : "r"(addr));
}
__device__ __forceinline__ float2 unpack2(u64 v) {
    float2 f; asm("mov.b64 {%0, %1}, %2;" : "=f"(f.x), "=f"(f.y) : "l"(v)); return f;
}
__device__ __forceinline__ float sig_f(float x) {
    return __fdividef(1.f, 1.f + __expf(-x));
}
__device__ __forceinline__ float tanh_f(float x) {
    return __fdividef(2.f, 1.f + __expf(-2.f * x)) - 1.f;
}

#define CP16(dst, src) asm volatile("cp.async.ca.shared.global [%0], [%1], 16;" :: "r"(dst), "l"(src))
#define CP_COMMIT()    asm volatile("cp.async.commit_group;")

// ============================ au counting sort ======================================
__global__ void zero_cnt_kernel() {
    if (threadIdx.x < 5) g_cnt[threadIdx.x] = 0;
}
__global__ __launch_bounds__(512)
void hist_kernel(const int* __restrict__ au) {
    __shared__ int h[5];
    int tid = threadIdx.x;
    if (tid < 5) h[tid] = 0;
    __syncthreads();
    atomicAdd(&h[5 - au[blockIdx.x * 512 + tid]], 1);
    __syncthreads();
    if (tid < 5) atomicAdd(&g_cnt[tid], h[tid]);
}
__global__ void prefix_kernel() {
    if (threadIdx.x == 0) {
        int s = 0;
        #pragma unroll
        for (int i = 0; i < 5; i++) { int c = g_cnt[i]; g_cursor[i] = s; s += c; }
    }
}
__global__ __launch_bounds__(512)
void scatter_kernel(const int* __restrict__ au) {
    int i = blockIdx.x * 512 + threadIdx.x;
    int lane = threadIdx.x & 31;
    int bkt = 5 - au[i];
    unsigned m = __match_any_sync(0xffffffffu, bkt);
    int leader = __ffs(m) - 1;
    int rank = __popc(m & ((1u << lane) - 1u));
    int base = 0;
    if (lane == leader) base = atomicAdd(&g_cursor[bkt], __popc(m));
    base = __shfl_sync(0xffffffffu, base, leader);
    g_perm[base + rank] = i;
}

// ============================ Kernel 1: fused MLP ===================================
// 64 rows/CTA, 256 threads, 2 CTA/SM. Thread tile 4 rows x 4 cols.
// LN1/LN2 are IN-REGISTER epilogues: row stats via 16-lane shfl_xor reduction
// (a GEMM output row is owned by exactly 16 consecutive lanes of one warp).
__global__ __launch_bounds__(256)
void mlp_kernel(const float* __restrict__ ud, const float* __restrict__ act,
                const float* __restrict__ ln0g, const float* __restrict__ ln0b,
                const float* __restrict__ W1, const float* __restrict__ b1,
                const float* __restrict__ ln1g, const float* __restrict__ ln1b,
                const float* __restrict__ W2, const float* __restrict__ b2,
                const float* __restrict__ ln2g, const float* __restrict__ ln2b)
{
    float* sW  = smem;                 // 8192 floats (W1, then W2)
    float* sX  = sW + 128 * 64;        // 64 * 132
    float* sX2 = sX + 64 * 132;        // 64 * 100
    float* sP  = sX2 + 64 * 100;       // 640

    const unsigned sW_a = (unsigned)__cvta_generic_to_shared(sW);
    const int tid = threadIdx.x;

    #pragma unroll
    for (int j = 0; j < 8; j++) {
        int f = tid + j * 256;
        reinterpret_cast<float4*>(sW)[f] = reinterpret_cast<const float4*>(W1)[f];
    }
    if (tid < 128) { sP[tid] = ln0g[tid]; sP[128 + tid] = ln0b[tid]; }
    if (tid < 64) {
        sP[256 + tid] = b1[tid];  sP[320 + tid] = ln1g[tid]; sP[384 + tid] = ln1b[tid];
        sP[448 + tid] = b2[tid];  sP[512 + tid] = ln2g[tid]; sP[576 + tid] = ln2b[tid];
    }

    const int r0 = blockIdx.x * 64;

    #pragma unroll
    for (int j = 0; j < 8; j++) {
        int f = tid + j * 256;
        int row = f >> 5, c4 = f & 31;
        float4 v = reinterpret_cast<const float4*>(ud + (size_t)(r0 + row) * 128)[c4];
        *reinterpret_cast<float4*>(&sX[row * 132 + c4 * 4]) = v;
    }
    #pragma unroll
    for (int j = 0; j < 2; j++) {
        int f = tid + j * 256;
        int row = f >> 3, c4 = f & 7;
        float4 v = reinterpret_cast<const float4*>(act + (size_t)(r0 + row) * 32)[c4];
        *reinterpret_cast<float4*>(&sX2[row * 100 + 64 + c4 * 4]) = v;
    }
    __syncthreads();

    const int w = tid >> 5, lane = tid & 31;

    // LN0 over 128 features (warp per row, 8 rows/warp)
    for (int rr = 0; rr < 8; rr++) {
        int row = w * 8 + rr;
        float v0 = sX[row * 132 + lane];
        float v1 = sX[row * 132 + lane + 32];
        float v2 = sX[row * 132 + lane + 64];
        float v3 = sX[row * 132 + lane + 96];
        float s = v0 + v1 + v2 + v3;
        float q = v0 * v0 + v1 * v1 + v2 * v2 + v3 * v3;
        #pragma unroll
        for (int o = 16; o; o >>= 1) { s += __shfl_xor_sync(~0u, s, o); q += __shfl_xor_sync(~0u, q, o); }
        float m = s * (1.f / 128.f);
        float var = q * (1.f / 128.f) - m * m;
        float rs = rsqrtf(var + EPSf);
        sX[row * 132 + lane]      = (v0 - m) * rs * sP[lane]      + sP[128 + lane];
        sX[row * 132 + lane + 32] = (v1 - m) * rs * sP[lane + 32] + sP[128 + lane + 32];
        sX[row * 132 + lane + 64] = (v2 - m) * rs * sP[lane + 64] + sP[128 + lane + 64];
        sX[row * 132 + lane + 96] = (v3 - m) * rs * sP[lane + 96] + sP[128 + lane + 96];
    }
    __syncthreads();

    const int ty = tid >> 4, tx = tid & 15;
    const int ry = ty * 4, cx = tx * 4;

    // GEMM1: (64x128)@(128x64)
    u64 acc[4][2];
    #pragma unroll
    for (int i = 0; i < 4; i++) { acc[i][0] = 0ull; acc[i][1] = 0ull; }

    for (int k = 0; k < 128; k += 4) {
        float4 a4[4];
        #pragma unroll
        for (int i = 0; i < 4; i++)
            a4[i] = *reinterpret_cast<const float4*>(&sX[(ry + i) * 132 + k]);
        u64 w0[4], w1[4];
        #pragma unroll
        for (int kk = 0; kk < 4; kk++)
            lds_v2u64(w0[kk], w1[kk], sW_a + (unsigned)((k + kk) * 64 + cx) * 4u);
        #pragma unroll
        for (int kk = 0; kk < 4; kk++) {
            #pragma unroll
            for (int i = 0; i < 4; i++) {
                u64 s = splat2((&a4[i].x)[kk]);
                ffma2(acc[i][0], s, w0[kk]);
                ffma2(acc[i][1], s, w1[kk]);
            }
        }
    }
    __syncthreads();   // sW(W1)+sX reads done

    // load W2 while epilogue runs
    #pragma unroll
    for (int j = 0; j < 6; j++) {
        int f = tid + j * 256;
        reinterpret_cast<float4*>(sW)[f] = reinterpret_cast<const float4*>(W2)[f];
    }

    // ---- in-register LN1 + relu -> sX2 cols [0,64) ----
    {
        float g0 = sP[320 + cx], g1 = sP[320 + cx + 1], g2 = sP[320 + cx + 2], g3 = sP[320 + cx + 3];
        float c0 = sP[384 + cx], c1 = sP[384 + cx + 1], c2 = sP[384 + cx + 2], c3 = sP[384 + cx + 3];
        float b0 = sP[256 + cx], b1v = sP[256 + cx + 1], b2v = sP[256 + cx + 2], b3 = sP[256 + cx + 3];
        #pragma unroll
        for (int i = 0; i < 4; i++) {
            float2 p0 = unpack2(acc[i][0]);
            float2 p1 = unpack2(acc[i][1]);
            float v0 = p0.x + b0, v1 = p0.y + b1v, v2 = p1.x + b2v, v3 = p1.y + b3;
            float s = v0 + v1 + v2 + v3;
            float q = v0 * v0 + v1 * v1 + v2 * v2 + v3 * v3;
            #pragma unroll
            for (int o = 1; o < 16; o <<= 1) { s += __shfl_xor_sync(~0u, s, o); q += __shfl_xor_sync(~0u, q, o); }
            float m = s * (1.f / 64.f);
            float var = q * (1.f / 64.f) - m * m;
            float rs = rsqrtf(var + EPSf);
            float4 o4;
            o4.x = fmaxf((v0 - m) * rs * g0 + c0, 0.f);
            o4.y = fmaxf((v1 - m) * rs * g1 + c1, 0.f);
            o4.z = fmaxf((v2 - m) * rs * g2 + c2, 0.f);
            o4.w = fmaxf((v3 - m) * rs * g3 + c3, 0.f);
            *reinterpret_cast<float4*>(&sX2[(ry + i) * 100 + cx]) = o4;
        }
    }
    __syncthreads();   // W2 + sX2 ready

    // GEMM2: (64x96)@(96x64)
    u64 acc2[4][2];
    #pragma unroll
    for (int i = 0; i < 4; i++) { acc2[i][0] = 0ull; acc2[i][1] = 0ull; }

    for (int k = 0; k < 96; k += 4) {
        float4 a4[4];
        #pragma unroll
        for (int i = 0; i < 4; i++)
            a4[i] = *reinterpret_cast<const float4*>(&sX2[(ry + i) * 100 + k]);
        u64 w0[4], w1[4];
        #pragma unroll
        for (int kk = 0; kk < 4; kk++)
            lds_v2u64(w0[kk], w1[kk], sW_a + (unsigned)((k + kk) * 64 + cx) * 4u);
        #pragma unroll
        for (int kk = 0; kk < 4; kk++) {
            #pragma unroll
            for (int i = 0; i < 4; i++) {
                u64 s = splat2((&a4[i].x)[kk]);
                ffma2(acc2[i][0], s, w0[kk]);
                ffma2(acc2[i][1], s, w1[kk]);
            }
        }
    }

    // ---- in-register LN2 + relu -> g_x (no barrier needed; regs only) ----
    {
        float g0 = sP[512 + cx], g1 = sP[512 + cx + 1], g2 = sP[512 + cx + 2], g3 = sP[512 + cx + 3];
        float c0 = sP[576 + cx], c1 = sP[576 + cx + 1], c2 = sP[576 + cx + 2], c3 = sP[576 + cx + 3];
        float b0 = sP[448 + cx], b1v = sP[448 + cx + 1], b2v = sP[448 + cx + 2], b3 = sP[448 + cx + 3];
        #pragma unroll
        for (int i = 0; i < 4; i++) {
            float2 p0 = unpack2(acc2[i][0]);
            float2 p1 = unpack2(acc2[i][1]);
            float v0 = p0.x + b0, v1 = p0.y + b1v, v2 = p1.x + b2v, v3 = p1.y + b3;
            float s = v0 + v1 + v2 + v3;
            float q = v0 * v0 + v1 * v1 + v2 * v2 + v3 * v3;
            #pragma unroll
            for (int o = 1; o < 16; o <<= 1) { s += __shfl_xor_sync(~0u, s, o); q += __shfl_xor_sync(~0u, q, o); }
            float m = s * (1.f / 64.f);
            float var = q * (1.f / 64.f) - m * m;
            float rs = rsqrtf(var + EPSf);
            float4 o4;
            o4.x = fmaxf((v0 - m) * rs * g0 + c0, 0.f);
            o4.y = fmaxf((v1 - m) * rs * g1 + c1, 0.f);
            o4.z = fmaxf((v2 - m) * rs * g2 + c2, 0.f);
            o4.w = fmaxf((v3 - m) * rs * g3 + c3, 0.f);
            *reinterpret_cast<float4*>(&g_x[(size_t)(r0 + ry + i) * 64 + cx]) = o4;
        }
    }
}

// ===================== Kernel 2: persistent bidirectional LSTM (R6, proven) =========
__global__ __launch_bounds__(512, 1)
void lstm_persistent_kernel(const float* __restrict__ fw_k, const float* __restrict__ fw_b,
                            const float* __restrict__ bw_k, const float* __restrict__ bw_b,
                            const int* __restrict__ au)
{
    float* sKp  = smem;                  // 32768
    float* xbuf = smem + 32768;          // 2 x 128 x 64
    float* sH   = smem + 49152;          // 128 x 66
    int*   sAu  = (int*)(smem + 57600);  // 128
    int*   sPb  = sAu + 128;             // 128

    const unsigned sKp_a = (unsigned)__cvta_generic_to_shared(sKp);

    const int dir = blockIdx.y;
    const float* K    = dir ? bw_k : fw_k;
    const float* bias = dir ? bw_b : fw_b;
    float* gy = g_ys[dir];

    const int b0  = blockIdx.x * 128;
    const int tid = threadIdx.x;
    const int tx  = tid & 31;
    const int ty  = tid >> 5;
    const int hx  = tx * 2;
    const int r0  = ty * 8;

    const int mx = au[g_perm[b0]];

    {
        int row = tid >> 2, seg = tid & 3;
        int pb = g_perm[b0 + row];
        int a = au[pb];
        #pragma unroll
        for (int tt = 0; tt < 2; tt++) {
            int ts = dir ? ((tt < a) ? (a - 1 - tt) : tt) : tt;
            const float* src = g_x + ((size_t)pb * 5 + ts) * 64 + seg * 16;
            unsigned dst = (unsigned)__cvta_generic_to_shared(xbuf + (tt & 1) * 8192 + row * 64 + seg * 16);
            #pragma unroll
            for (int q = 0; q < 4; q++) CP16(dst + q * 16, src + q * 4);
            CP_COMMIT();
        }
        if (seg == 0) { sAu[row] = a; sPb[row] = pb; }
    }

    #pragma unroll
    for (int it = 0; it < 16; it++) {
        int f = tid + it * 512;
        int kk = f >> 6, c4 = f & 63;
        float4 v = reinterpret_cast<const float4*>(K + (size_t)kk * 256)[c4];
        int g     = c4 >> 4;
        int p     = (c4 & 15) * 2;
        int plane = g >> 1;
        int gpos  = (g & 1) * 2;
        *reinterpret_cast<float2*>(&sKp[kk * 256 + plane * 128 + p * 4 + gpos])       = make_float2(v.x, v.y);
        *reinterpret_cast<float2*>(&sKp[kk * 256 + plane * 128 + (p + 1) * 4 + gpos]) = make_float2(v.z, v.w);
    }

    float2 bg[4];
    #pragma unroll
    for (int g = 0; g < 4; g++)
        bg[g] = *reinterpret_cast<const float2*>(bias + g * 64 + hx);

    float2 cc[8];
    #pragma unroll
    for (int i = 0; i < 8; i++) cc[i] = make_float2(0.f, 0.f);

    const unsigned wbase = sKp_a + (unsigned)(tx * 4) * 4u;

    for (int t = 0; t < mx; t++) {
        asm volatile("cp.async.wait_group 1;" ::: "memory");
        __syncthreads();

        const float* xb = xbuf + (t & 1) * 8192;

        u64 acc[8][4];
        #pragma unroll
        for (int i = 0; i < 8; i++)
            #pragma unroll
            for (int g = 0; g < 4; g++) acc[i][g] = 0ull;

        #pragma unroll 2
        for (int k = 0; k < 64; k += 2) {
            u64 wi0, wj0, wf0, wo0, wi1, wj1, wf1, wo1;
            lds_v2u64(wi0, wj0, wbase + (unsigned)(k * 256) * 4u);
            lds_v2u64(wf0, wo0, wbase + (unsigned)(k * 256 + 128) * 4u);
            lds_v2u64(wi1, wj1, wbase + (unsigned)((k + 1) * 256) * 4u);
            lds_v2u64(wf1, wo1, wbase + (unsigned)((k + 1) * 256 + 128) * 4u);
            #pragma unroll
            for (int i = 0; i < 8; i++) {
                float2 a = *reinterpret_cast<const float2*>(&xb[(r0 + i) * 64 + k]);
                u64 sx = splat2(a.x), sy = splat2(a.y);
                ffma2(acc[i][0], sx, wi0); ffma2(acc[i][1], sx, wj0);
                ffma2(acc[i][2], sx, wf0); ffma2(acc[i][3], sx, wo0);
                ffma2(acc[i][0], sy, wi1); ffma2(acc[i][1], sy, wj1);
                ffma2(acc[i][2], sy, wf1); ffma2(acc[i][3], sy, wo1);
            }
        }

        if (t > 0) {
            #pragma unroll 2
            for (int k = 0; k < 64; k += 2) {
                u64 wi0, wj0, wf0, wo0, wi1, wj1, wf1, wo1;
                lds_v2u64(wi0, wj0, wbase + (unsigned)((k + 64) * 256) * 4u);
                lds_v2u64(wf0, wo0, wbase + (unsigned)((k + 64) * 256 + 128) * 4u);
                lds_v2u64(wi1, wj1, wbase + (unsigned)((k + 65) * 256) * 4u);
                lds_v2u64(wf1, wo1, wbase + (unsigned)((k + 65) * 256 + 128) * 4u);
                #pragma unroll
                for (int i = 0; i < 8; i++) {
                    float2 a = *reinterpret_cast<const float2*>(&sH[(r0 + i) * 66 + k]);
                    u64 sx = splat2(a.x), sy = splat2(a.y);
                    ffma2(acc[i][0], sx, wi0); ffma2(acc[i][1], sx, wj0);
                    ffma2(acc[i][2], sx, wf0); ffma2(acc[i][3], sx, wo0);
                    ffma2(acc[i][0], sy, wi1); ffma2(acc[i][1], sy, wj1);
                    ffma2(acc[i][2], sy, wf1); ffma2(acc[i][3], sy, wo1);
                }
            }
        }

        __syncthreads();

        if (t + 2 < mx) {
            int row = tid >> 2, seg = tid & 3;
            int pb = sPb[row];
            int tt = t + 2;
            int a = sAu[row];
            int ts = dir ? ((tt < a) ? (a - 1 - tt) : tt) : tt;
            const float* src = g_x + ((size_t)pb * 5 + ts) * 64 + seg * 16;
            unsigned dst = (unsigned)__cvta_generic_to_shared(xbuf + (tt & 1) * 8192 + row * 64 + seg * 16);
            #pragma unroll
            for (int q = 0; q < 4; q++) CP16(dst + q * 16, src + q * 4);
            CP_COMMIT();
        }

        #pragma unroll
        for (int i = 0; i < 8; i++) {
            int row = r0 + i;
            int a = sAu[row];
            bool valid = (t < a);
            float2 gi = unpack2(acc[i][0]);
            float2 gj = unpack2(acc[i][1]);
            float2 gf = unpack2(acc[i][2]);
            float2 go = unpack2(acc[i][3]);
            gi.x += bg[0].x; gi.y += bg[0].y;
            gj.x += bg[1].x; gj.y += bg[1].y;
            gf.x += bg[2].x; gf.y += bg[2].y;
            go.x += bg[3].x; go.y += bg[3].y;

            float2 hold = (t > 0) ? *reinterpret_cast<const float2*>(&sH[row * 66 + hx])
                                  : make_float2(0.f, 0.f);
            float2 cold = cc[i];

            float cnx = sig_f(gf.x + 1.f) * cold.x + sig_f(gi.x) * tanh_f(gj.x);
            float cny = sig_f(gf.y + 1.f) * cold.y + sig_f(gi.y) * tanh_f(gj.y);
            float hnx = sig_f(go.x) * tanh_f(cnx);
            float hny = sig_f(go.y) * tanh_f(cny);

            cc[i].x = valid ? cnx : cold.x;
            cc[i].y = valid ? cny : cold.y;
            float2 hw = make_float2(valid ? hnx : hold.x, valid ? hny : hold.y);
            *reinterpret_cast<float2*>(&sH[row * 66 + hx]) = hw;

            float2 yw = make_float2(valid ? hnx : 0.f, valid ? hny : 0.f);
            *reinterpret_cast<float2*>(gy + ((size_t)sPb[row] * 5 + t) * 64 + hx) = yw;
        }
    }
    asm volatile("cp.async.wait_group 0;" ::: "memory");
}

// ============================ Kernel 3: final =======================================
__global__ __launch_bounds__(256)
void final_kernel(const float* __restrict__ mask,
                  const float* __restrict__ ln3g, const float* __restrict__ ln3b,
                  const float* __restrict__ convw, const float* __restrict__ convb,
                  const int* __restrict__ au, float* __restrict__ out)
{
    int b = blockIdx.x * 8 + (threadIdx.x >> 5);
    int lane = threadIdx.x & 31;
    int a = au[b];

    float vals[20];
    float s = 0.f, q = 0.f;
    #pragma unroll
    for (int t = 0; t < 5; t++) {
        float v0 = 0.f, v1 = 0.f, v2 = 0.f, v3 = 0.f;
        if (t < a) {
            int rt = a - 1 - t;
            size_t fbase = ((size_t)b * 5 + t)  * 64;
            size_t bbase = ((size_t)b * 5 + rt) * 64;
            v0 = g_ys[0][fbase + lane];
            v1 = g_ys[0][fbase + lane + 32];
            v2 = g_ys[1][bbase + lane];
            v3 = g_ys[1][bbase + lane + 32];
        }
        vals[t * 4 + 0] = v0; vals[t * 4 + 1] = v1;
        vals[t * 4 + 2] = v2; vals[t * 4 + 3] = v3;
        s += v0 + v1 + v2 + v3;
        q += v0 * v0 + v1 * v1 + v2 * v2 + v3 * v3;
    }
    #pragma unroll
    for (int o = 16; o; o >>= 1) { s += __shfl_xor_sync(~0u, s, o); q += __shfl_xor_sync(~0u, q, o); }
    float m = s * (1.f / 640.f);
    float var = q * (1.f / 640.f) - m * m;
    float rs = rsqrtf(var + EPSf);

    float g0 = ln3g[lane],      c0 = ln3b[lane],      w0 = convw[lane];
    float g1 = ln3g[lane + 32], c1 = ln3b[lane + 32], w1 = convw[lane + 32];
    float g2 = ln3g[lane + 64], c2 = ln3b[lane + 64], w2 = convw[lane + 64];
    float g3 = ln3g[lane + 96], c3 = ln3b[lane + 96], w3 = convw[lane + 96];

    float accq = 0.f, msum = 0.f;
    #pragma unroll
    for (int t = 0; t < 5; t++) {
        float p =
            fmaxf((vals[t*4+0] - m) * rs * g0 + c0, 0.f) * w0 +
            fmaxf((vals[t*4+1] - m) * rs * g1 + c1, 0.f) * w1 +
            fmaxf((vals[t*4+2] - m) * rs * g2 + c2, 0.f) * w2 +
            fmaxf((vals[t*4+3] - m) * rs * g3 + c3, 0.f) * w3;
        float mk = mask[(size_t)b * 5 + t];
        accq += p * mk;
        msum += mk;
    }
    #pragma unroll
    for (int o = 16; o; o >>= 1) accq += __shfl_xor_sync(~0u, accq, o);
    if (lane == 0) out[b] = accq + convb[0] * msum;
}

// =====================================================================================
extern "C" void kernel_launch(void* const* d_in, const int* in_sizes, int n_in,
                              void* d_out, int out_size)
{
    (void)in_sizes; (void)n_in; (void)out_size;
    const float* ud     = (const float*)d_in[0];
    const float* action = (const float*)d_in[1];
    const float* mask   = (const float*)d_in[2];
    const float* ln0g   = (const float*)d_in[3];
    const float* ln0b   = (const float*)d_in[4];
    const float* W1     = (const float*)d_in[5];
    const float* b1     = (const float*)d_in[6];
    const float* ln1g   = (const float*)d_in[7];
    const float* ln1b   = (const float*)d_in[8];
    const float* W2     = (const float*)d_in[9];
    const float* b2     = (const float*)d_in[10];
    const float* ln2g   = (const float*)d_in[11];
    const float* ln2b   = (const float*)d_in[12];
    const float* fw_k   = (const float*)d_in[13];
    const float* fw_b   = (const float*)d_in[14];
    const float* bw_k   = (const float*)d_in[15];
    const float* bw_b   = (const float*)d_in[16];
    const float* ln3g   = (const float*)d_in[17];
    const float* ln3b   = (const float*)d_in[18];
    const float* convw  = (const float*)d_in[19];
    const float* convb  = (const float*)d_in[20];
    const int*   au     = (const int*)d_in[21];

    const int MLP_SMEM  = (128*64 + 64*132 + 64*100 + 640) * 4;   // 94720 B
    const int LSTM_SMEM = (57728 + 256) * 4;                      // 231936 B

    cudaFuncSetAttribute(mlp_kernel,             cudaFuncAttributeMaxDynamicSharedMemorySize, MLP_SMEM);
    cudaFuncSetAttribute(lstm_persistent_kernel, cudaFuncAttributeMaxDynamicSharedMemorySize, LSTM_SMEM);

    zero_cnt_kernel<<<1, 32>>>();
    hist_kernel<<<Bn / 512, 512>>>(au);
    prefix_kernel<<<1, 32>>>();
    scatter_kernel<<<Bn / 512, 512>>>(au);

    mlp_kernel<<<BT / 64, 256, MLP_SMEM>>>(ud, action, ln0g, ln0b, W1, b1,
                                           ln1g, ln1b, W2, b2, ln2g, ln2b);

    lstm_persistent_kernel<<<dim3(Bn / 128, 2), 512, LSTM_SMEM>>>(fw_k, fw_b, bw_k, bw_b, au);

    final_kernel<<<Bn / 8, 256>>>(mask, ln3g, ln3b, convw, convb, au, (float*)d_out);
}

// round 9
// speedup vs baseline: 1.1571x; 1.1571x over previous
#include <cuda_runtime.h>
#include <math.h>

#define Bn   65536
#define Tn   5
#define BT   (Bn*Tn)
#define EPSf 1e-12f

typedef unsigned long long u64;

__device__ float g_x[BT * 64];          // zero-init; invalid (t>=au) slots NEVER written -> stay 0
__device__ float g_ys[2][BT * 64];
__device__ int   g_cnt[5];
__device__ int   g_cursor[5];
__device__ int   g_pbase[5];            // perm base per bucket (saved before scatter mutates cursor)
__device__ int   g_vbase[6];            // cumulative valid-row (b,t) counts per bucket; [5] = total
__device__ int   g_perm[Bn];

extern __shared__ float smem[];

__device__ __forceinline__ u64 splat2(float x) {
    u64 r; asm("mov.b64 %0, {%1, %1};" : "=l"(r) : "f"(x)); return r;
}
__device__ __forceinline__ void ffma2(u64& d, u64 a, u64 b) {
    asm("fma.rn.f32x2 %0, %1, %2, %0;" : "+l"(d) : "l"(a), "l"(b));
}
__device__ __forceinline__ void lds_v2u64(u64& a, u64& b, unsigned addr) {
    asm volatile("ld.shared.v2.u64 {%0, %1}, [%2];" : "=l"(a), "=l"(b) : "r"(addr));
}
__device__ __forceinline__ float2 unpack2(u64 v) {
    float2 f; asm("mov.b64 {%0, %1}, %2;" : "=f"(f.x), "=f"(f.y) : "l"(v)); return f;
}
__device__ __forceinline__ float sig_f(float x) {
    return __fdividef(1.f, 1.f + __expf(-x));
}
__device__ __forceinline__ float tanh_f(float x) {
    return __fdividef(2.f, 1.f + __expf(-2.f * x)) - 1.f;
}

#define CP16(dst, src) asm volatile("cp.async.ca.shared.global [%0], [%1], 16;" :: "r"(dst), "l"(src))
#define CP_COMMIT()    asm volatile("cp.async.commit_group;")

// ============================ au counting sort ======================================
__global__ void zero_cnt_kernel() {
    if (threadIdx.x < 5) g_cnt[threadIdx.x] = 0;
}
__global__ __launch_bounds__(512)
void hist_kernel(const int* __restrict__ au) {
    __shared__ int h[5];
    int tid = threadIdx.x;
    if (tid < 5) h[tid] = 0;
    __syncthreads();
    atomicAdd(&h[5 - au[blockIdx.x * 512 + tid]], 1);
    __syncthreads();
    if (tid < 5) atomicAdd(&g_cnt[tid], h[tid]);
}
__global__ void prefix_kernel() {
    if (threadIdx.x == 0) {
        int s = 0, vs = 0;
        #pragma unroll
        for (int i = 0; i < 5; i++) {
            int c = g_cnt[i];
            g_cursor[i] = s;
            g_pbase[i]  = s;
            g_vbase[i]  = vs;
            s  += c;
            vs += c * (5 - i);      // bucket i holds au == 5-i
        }
        g_vbase[5] = vs;
    }
}
__global__ __launch_bounds__(512)
void scatter_kernel(const int* __restrict__ au) {
    int i = blockIdx.x * 512 + threadIdx.x;
    int lane = threadIdx.x & 31;
    int bkt = 5 - au[i];
    unsigned m = __match_any_sync(0xffffffffu, bkt);
    int leader = __ffs(m) - 1;
    int rank = __popc(m & ((1u << lane) - 1u));
    int base = 0;
    if (lane == leader) base = atomicAdd(&g_cursor[bkt], __popc(m));
    base = __shfl_sync(0xffffffffu, base, leader);
    g_perm[base + rank] = i;
}

// ============================ Kernel 1: fused MLP over VALID rows only ==============
// 64 valid (b,t) rows per CTA; CTAs past the valid total exit immediately (~40% skip).
// Row mapping: flat valid index -> au-bucket -> (b = perm[...], t). Invalid g_x slots
// are never written and remain 0 (zero-init), read only by discarded LSTM lanes.
__global__ __launch_bounds__(256)
void mlp_kernel(const float* __restrict__ ud, const float* __restrict__ act,
                const float* __restrict__ ln0g, const float* __restrict__ ln0b,
                const float* __restrict__ W1, const float* __restrict__ b1,
                const float* __restrict__ ln1g, const float* __restrict__ ln1b,
                const float* __restrict__ W2, const float* __restrict__ b2,
                const float* __restrict__ ln2g, const float* __restrict__ ln2b)
{
    const int vtot = g_vbase[5];
    if (blockIdx.x * 64 >= vtot) return;

    float* sW  = smem;                 // 8192 floats (W1, then W2)
    float* sX  = sW + 128 * 64;        // 64 * 132
    float* sX2 = sX + 64 * 132;        // 64 * 100
    float* sP  = sX2 + 64 * 100;       // 640
    int*   sRowIdx = (int*)(sP + 640); // 64: global row index b*5+t, or -1

    const unsigned sW_a = (unsigned)__cvta_generic_to_shared(sW);
    const int tid = threadIdx.x;

    #pragma unroll
    for (int j = 0; j < 8; j++) {
        int f = tid + j * 256;
        reinterpret_cast<float4*>(sW)[f] = reinterpret_cast<const float4*>(W1)[f];
    }
    if (tid < 128) { sP[tid] = ln0g[tid]; sP[128 + tid] = ln0b[tid]; }
    if (tid < 64) {
        sP[256 + tid] = b1[tid];  sP[320 + tid] = ln1g[tid]; sP[384 + tid] = ln1b[tid];
        sP[448 + tid] = b2[tid];  sP[512 + tid] = ln2g[tid]; sP[576 + tid] = ln2b[tid];
    }

    // ---- map 64 flat valid indices -> global rows ----
    if (tid < 64) {
        int v = blockIdx.x * 64 + tid;
        int row = -1;
        if (v < vtot) {
            int k = 0;
            #pragma unroll
            for (int j = 1; j < 5; j++) if (v >= g_vbase[j]) k = j;
            int L = 5 - k;
            int idx = v - g_vbase[k];
            int q = idx / L;
            int t = idx - q * L;
            int b = g_perm[g_pbase[k] + q];
            row = b * 5 + t;
        }
        sRowIdx[tid] = row;
    }
    __syncthreads();

    #pragma unroll
    for (int j = 0; j < 8; j++) {
        int f = tid + j * 256;
        int row = f >> 5, c4 = f & 31;
        int gr = sRowIdx[row];
        float4 v = make_float4(0.f, 0.f, 0.f, 0.f);
        if (gr >= 0) v = reinterpret_cast<const float4*>(ud + (size_t)gr * 128)[c4];
        *reinterpret_cast<float4*>(&sX[row * 132 + c4 * 4]) = v;
    }
    #pragma unroll
    for (int j = 0; j < 2; j++) {
        int f = tid + j * 256;
        int row = f >> 3, c4 = f & 7;
        int gr = sRowIdx[row];
        float4 v = make_float4(0.f, 0.f, 0.f, 0.f);
        if (gr >= 0) v = reinterpret_cast<const float4*>(act + (size_t)gr * 32)[c4];
        *reinterpret_cast<float4*>(&sX2[row * 100 + 64 + c4 * 4]) = v;
    }
    __syncthreads();

    const int w = tid >> 5, lane = tid & 31;

    // LN0 over 128 features (warp per row, 8 rows/warp)
    for (int rr = 0; rr < 8; rr++) {
        int row = w * 8 + rr;
        float v0 = sX[row * 132 + lane];
        float v1 = sX[row * 132 + lane + 32];
        float v2 = sX[row * 132 + lane + 64];
        float v3 = sX[row * 132 + lane + 96];
        float s = v0 + v1 + v2 + v3;
        float q = v0 * v0 + v1 * v1 + v2 * v2 + v3 * v3;
        #pragma unroll
        for (int o = 16; o; o >>= 1) { s += __shfl_xor_sync(~0u, s, o); q += __shfl_xor_sync(~0u, q, o); }
        float m = s * (1.f / 128.f);
        float var = q * (1.f / 128.f) - m * m;
        float rs = rsqrtf(var + EPSf);
        sX[row * 132 + lane]      = (v0 - m) * rs * sP[lane]      + sP[128 + lane];
        sX[row * 132 + lane + 32] = (v1 - m) * rs * sP[lane + 32] + sP[128 + lane + 32];
        sX[row * 132 + lane + 64] = (v2 - m) * rs * sP[lane + 64] + sP[128 + lane + 64];
        sX[row * 132 + lane + 96] = (v3 - m) * rs * sP[lane + 96] + sP[128 + lane + 96];
    }
    __syncthreads();

    const int ty = tid >> 4, tx = tid & 15;
    const int ry = ty * 4, cx = tx * 4;

    // GEMM1: (64x128)@(128x64)
    u64 acc[4][2];
    #pragma unroll
    for (int i = 0; i < 4; i++) { acc[i][0] = 0ull; acc[i][1] = 0ull; }

    for (int k = 0; k < 128; k += 4) {
        float4 a4[4];
        #pragma unroll
        for (int i = 0; i < 4; i++)
            a4[i] = *reinterpret_cast<const float4*>(&sX[(ry + i) * 132 + k]);
        u64 w0[4], w1[4];
        #pragma unroll
        for (int kk = 0; kk < 4; kk++)
            lds_v2u64(w0[kk], w1[kk], sW_a + (unsigned)((k + kk) * 64 + cx) * 4u);
        #pragma unroll
        for (int kk = 0; kk < 4; kk++) {
            #pragma unroll
            for (int i = 0; i < 4; i++) {
                u64 s = splat2((&a4[i].x)[kk]);
                ffma2(acc[i][0], s, w0[kk]);
                ffma2(acc[i][1], s, w1[kk]);
            }
        }
    }
    __syncthreads();   // sW(W1)+sX reads done

    // load W2 while epilogue runs
    #pragma unroll
    for (int j = 0; j < 6; j++) {
        int f = tid + j * 256;
        reinterpret_cast<float4*>(sW)[f] = reinterpret_cast<const float4*>(W2)[f];
    }

    // ---- in-register LN1 + relu -> sX2 cols [0,64) ----
    {
        float g0 = sP[320 + cx], g1 = sP[320 + cx + 1], g2 = sP[320 + cx + 2], g3 = sP[320 + cx + 3];
        float c0 = sP[384 + cx], c1 = sP[384 + cx + 1], c2 = sP[384 + cx + 2], c3 = sP[384 + cx + 3];
        float b0 = sP[256 + cx], b1v = sP[256 + cx + 1], b2v = sP[256 + cx + 2], b3 = sP[256 + cx + 3];
        #pragma unroll
        for (int i = 0; i < 4; i++) {
            float2 p0 = unpack2(acc[i][0]);
            float2 p1 = unpack2(acc[i][1]);
            float v0 = p0.x + b0, v1 = p0.y + b1v, v2 = p1.x + b2v, v3 = p1.y + b3;
            float s = v0 + v1 + v2 + v3;
            float q = v0 * v0 + v1 * v1 + v2 * v2 + v3 * v3;
            #pragma unroll
            for (int o = 1; o < 16; o <<= 1) { s += __shfl_xor_sync(~0u, s, o); q += __shfl_xor_sync(~0u, q, o); }
            float m = s * (1.f / 64.f);
            float var = q * (1.f / 64.f) - m * m;
            float rs = rsqrtf(var + EPSf);
            float4 o4;
            o4.x = fmaxf((v0 - m) * rs * g0 + c0, 0.f);
            o4.y = fmaxf((v1 - m) * rs * g1 + c1, 0.f);
            o4.z = fmaxf((v2 - m) * rs * g2 + c2, 0.f);
            o4.w = fmaxf((v3 - m) * rs * g3 + c3, 0.f);
            *reinterpret_cast<float4*>(&sX2[(ry + i) * 100 + cx]) = o4;
        }
    }
    __syncthreads();   // W2 + sX2 ready

    // GEMM2: (64x96)@(96x64)
    u64 acc2[4][2];
    #pragma unroll
    for (int i = 0; i < 4; i++) { acc2[i][0] = 0ull; acc2[i][1] = 0ull; }

    for (int k = 0; k < 96; k += 4) {
        float4 a4[4];
        #pragma unroll
        for (int i = 0; i < 4; i++)
            a4[i] = *reinterpret_cast<const float4*>(&sX2[(ry + i) * 100 + k]);
        u64 w0[4], w1[4];
        #pragma unroll
        for (int kk = 0; kk < 4; kk++)
            lds_v2u64(w0[kk], w1[kk], sW_a + (unsigned)((k + kk) * 64 + cx) * 4u);
        #pragma unroll
        for (int kk = 0; kk < 4; kk++) {
            #pragma unroll
            for (int i = 0; i < 4; i++) {
                u64 s = splat2((&a4[i].x)[kk]);
                ffma2(acc2[i][0], s, w0[kk]);
                ffma2(acc2[i][1], s, w1[kk]);
            }
        }
    }

    // ---- in-register LN2 + relu -> g_x (guarded scatter store) ----
    {
        float g0 = sP[512 + cx], g1 = sP[512 + cx + 1], g2 = sP[512 + cx + 2], g3 = sP[512 + cx + 3];
        float c0 = sP[576 + cx], c1 = sP[576 + cx + 1], c2 = sP[576 + cx + 2], c3 = sP[576 + cx + 3];
        float b0 = sP[448 + cx], b1v = sP[448 + cx + 1], b2v = sP[448 + cx + 2], b3 = sP[448 + cx + 3];
        #pragma unroll
        for (int i = 0; i < 4; i++) {
            float2 p0 = unpack2(acc2[i][0]);
            float2 p1 = unpack2(acc2[i][1]);
            float v0 = p0.x + b0, v1 = p0.y + b1v, v2 = p1.x + b2v, v3 = p1.y + b3;
            float s = v0 + v1 + v2 + v3;
            float q = v0 * v0 + v1 * v1 + v2 * v2 + v3 * v3;
            #pragma unroll
            for (int o = 1; o < 16; o <<= 1) { s += __shfl_xor_sync(~0u, s, o); q += __shfl_xor_sync(~0u, q, o); }
            float m = s * (1.f / 64.f);
            float var = q * (1.f / 64.f) - m * m;
            float rs = rsqrtf(var + EPSf);
            int gr = sRowIdx[ry + i];
            if (gr >= 0) {
                float4 o4;
                o4.x = fmaxf((v0 - m) * rs * g0 + c0, 0.f);
                o4.y = fmaxf((v1 - m) * rs * g1 + c1, 0.f);
                o4.z = fmaxf((v2 - m) * rs * g2 + c2, 0.f);
                o4.w = fmaxf((v3 - m) * rs * g3 + c3, 0.f);
                *reinterpret_cast<float4*>(&g_x[(size_t)gr * 64 + cx]) = o4;
            }
        }
    }
}

// ===================== Kernel 2: persistent bidirectional LSTM (R6, proven) =========
__global__ __launch_bounds__(512, 1)
void lstm_persistent_kernel(const float* __restrict__ fw_k, const float* __restrict__ fw_b,
                            const float* __restrict__ bw_k, const float* __restrict__ bw_b,
                            const int* __restrict__ au)
{
    float* sKp  = smem;                  // 32768
    float* xbuf = smem + 32768;          // 2 x 128 x 64
    float* sH   = smem + 49152;          // 128 x 66
    int*   sAu  = (int*)(smem + 57600);  // 128
    int*   sPb  = sAu + 128;             // 128

    const unsigned sKp_a = (unsigned)__cvta_generic_to_shared(sKp);

    const int dir = blockIdx.y;
    const float* K    = dir ? bw_k : fw_k;
    const float* bias = dir ? bw_b : fw_b;
    float* gy = g_ys[dir];

    const int b0  = blockIdx.x * 128;
    const int tid = threadIdx.x;
    const int tx  = tid & 31;
    const int ty  = tid >> 5;
    const int hx  = tx * 2;
    const int r0  = ty * 8;

    const int mx = au[g_perm[b0]];

    {
        int row = tid >> 2, seg = tid & 3;
        int pb = g_perm[b0 + row];
        int a = au[pb];
        #pragma unroll
        for (int tt = 0; tt < 2; tt++) {
            int ts = dir ? ((tt < a) ? (a - 1 - tt) : tt) : tt;
            const float* src = g_x + ((size_t)pb * 5 + ts) * 64 + seg * 16;
            unsigned dst = (unsigned)__cvta_generic_to_shared(xbuf + (tt & 1) * 8192 + row * 64 + seg * 16);
            #pragma unroll
            for (int q = 0; q < 4; q++) CP16(dst + q * 16, src + q * 4);
            CP_COMMIT();
        }
        if (seg == 0) { sAu[row] = a; sPb[row] = pb; }
    }

    #pragma unroll
    for (int it = 0; it < 16; it++) {
        int f = tid + it * 512;
        int kk = f >> 6, c4 = f & 63;
        float4 v = reinterpret_cast<const float4*>(K + (size_t)kk * 256)[c4];
        int g     = c4 >> 4;
        int p     = (c4 & 15) * 2;
        int plane = g >> 1;
        int gpos  = (g & 1) * 2;
        *reinterpret_cast<float2*>(&sKp[kk * 256 + plane * 128 + p * 4 + gpos])       = make_float2(v.x, v.y);
        *reinterpret_cast<float2*>(&sKp[kk * 256 + plane * 128 + (p + 1) * 4 + gpos]) = make_float2(v.z, v.w);
    }

    float2 bg[4];
    #pragma unroll
    for (int g = 0; g < 4; g++)
        bg[g] = *reinterpret_cast<const float2*>(bias + g * 64 + hx);

    float2 cc[8];
    #pragma unroll
    for (int i = 0; i < 8; i++) cc[i] = make_float2(0.f, 0.f);

    const unsigned wbase = sKp_a + (unsigned)(tx * 4) * 4u;

    for (int t = 0; t < mx; t++) {
        asm volatile("cp.async.wait_group 1;" ::: "memory");
        __syncthreads();

        const float* xb = xbuf + (t & 1) * 8192;

        u64 acc[8][4];
        #pragma unroll
        for (int i = 0; i < 8; i++)
            #pragma unroll
            for (int g = 0; g < 4; g++) acc[i][g] = 0ull;

        #pragma unroll 2
        for (int k = 0; k < 64; k += 2) {
            u64 wi0, wj0, wf0, wo0, wi1, wj1, wf1, wo1;
            lds_v2u64(wi0, wj0, wbase + (unsigned)(k * 256) * 4u);
            lds_v2u64(wf0, wo0, wbase + (unsigned)(k * 256 + 128) * 4u);
            lds_v2u64(wi1, wj1, wbase + (unsigned)((k + 1) * 256) * 4u);
            lds_v2u64(wf1, wo1, wbase + (unsigned)((k + 1) * 256 + 128) * 4u);
            #pragma unroll
            for (int i = 0; i < 8; i++) {
                float2 a = *reinterpret_cast<const float2*>(&xb[(r0 + i) * 64 + k]);
                u64 sx = splat2(a.x), sy = splat2(a.y);
                ffma2(acc[i][0], sx, wi0); ffma2(acc[i][1], sx, wj0);
                ffma2(acc[i][2], sx, wf0); ffma2(acc[i][3], sx, wo0);
                ffma2(acc[i][0], sy, wi1); ffma2(acc[i][1], sy, wj1);
                ffma2(acc[i][2], sy, wf1); ffma2(acc[i][3], sy, wo1);
            }
        }

        if (t > 0) {
            #pragma unroll 2
            for (int k = 0; k < 64; k += 2) {
                u64 wi0, wj0, wf0, wo0, wi1, wj1, wf1, wo1;
                lds_v2u64(wi0, wj0, wbase + (unsigned)((k + 64) * 256) * 4u);
                lds_v2u64(wf0, wo0, wbase + (unsigned)((k + 64) * 256 + 128) * 4u);
                lds_v2u64(wi1, wj1, wbase + (unsigned)((k + 65) * 256) * 4u);
                lds_v2u64(wf1, wo1, wbase + (unsigned)((k + 65) * 256 + 128) * 4u);
                #pragma unroll
                for (int i = 0; i < 8; i++) {
                    float2 a = *reinterpret_cast<const float2*>(&sH[(r0 + i) * 66 + k]);
                    u64 sx = splat2(a.x), sy = splat2(a.y);
                    ffma2(acc[i][0], sx, wi0); ffma2(acc[i][1], sx, wj0);
                    ffma2(acc[i][2], sx, wf0); ffma2(acc[i][3], sx, wo0);
                    ffma2(acc[i][0], sy, wi1); ffma2(acc[i][1], sy, wj1);
                    ffma2(acc[i][2], sy, wf1); ffma2(acc[i][3], sy, wo1);
                }
            }
        }

        __syncthreads();

        if (t + 2 < mx) {
            int row = tid >> 2, seg = tid & 3;
            int pb = sPb[row];
            int tt = t + 2;
            int a = sAu[row];
            int ts = dir ? ((tt < a) ? (a - 1 - tt) : tt) : tt;
            const float* src = g_x + ((size_t)pb * 5 + ts) * 64 + seg * 16;
            unsigned dst = (unsigned)__cvta_generic_to_shared(xbuf + (tt & 1) * 8192 + row * 64 + seg * 16);
            #pragma unroll
            for (int q = 0; q < 4; q++) CP16(dst + q * 16, src + q * 4);
            CP_COMMIT();
        }

        #pragma unroll
        for (int i = 0; i < 8; i++) {
            int row = r0 + i;
            int a = sAu[row];
            bool valid = (t < a);
            float2 gi = unpack2(acc[i][0]);
            float2 gj = unpack2(acc[i][1]);
            float2 gf = unpack2(acc[i][2]);
            float2 go = unpack2(acc[i][3]);
            gi.x += bg[0].x; gi.y += bg[0].y;
            gj.x += bg[1].x; gj.y += bg[1].y;
            gf.x += bg[2].x; gf.y += bg[2].y;
            go.x += bg[3].x; go.y += bg[3].y;

            float2 hold = (t > 0) ? *reinterpret_cast<const float2*>(&sH[row * 66 + hx])
                                  : make_float2(0.f, 0.f);
            float2 cold = cc[i];

            float cnx = sig_f(gf.x + 1.f) * cold.x + sig_f(gi.x) * tanh_f(gj.x);
            float cny = sig_f(gf.y + 1.f) * cold.y + sig_f(gi.y) * tanh_f(gj.y);
            float hnx = sig_f(go.x) * tanh_f(cnx);
            float hny = sig_f(go.y) * tanh_f(cny);

            cc[i].x = valid ? cnx : cold.x;
            cc[i].y = valid ? cny : cold.y;
            float2 hw = make_float2(valid ? hnx : hold.x, valid ? hny : hold.y);
            *reinterpret_cast<float2*>(&sH[row * 66 + hx]) = hw;

            float2 yw = make_float2(valid ? hnx : 0.f, valid ? hny : 0.f);
            *reinterpret_cast<float2*>(gy + ((size_t)sPb[row] * 5 + t) * 64 + hx) = yw;
        }
    }
    asm volatile("cp.async.wait_group 0;" ::: "memory");
}

// ============================ Kernel 3: final =======================================
__global__ __launch_bounds__(256)
void final_kernel(const float* __restrict__ mask,
                  const float* __restrict__ ln3g, const float* __restrict__ ln3b,
                  const float* __restrict__ convw, const float* __restrict__ convb,
                  const int* __restrict__ au, float* __restrict__ out)
{
    int b = blockIdx.x * 8 + (threadIdx.x >> 5);
    int lane = threadIdx.x & 31;
    int a = au[b];

    float vals[20];
    float s = 0.f, q = 0.f;
    #pragma unroll
    for (int t = 0; t < 5; t++) {
        float v0 = 0.f, v1 = 0.f, v2 = 0.f, v3 = 0.f;
        if (t < a) {
            int rt = a - 1 - t;
            size_t fbase = ((size_t)b * 5 + t)  * 64;
            size_t bbase = ((size_t)b * 5 + rt) * 64;
            v0 = g_ys[0][fbase + lane];
            v1 = g_ys[0][fbase + lane + 32];
            v2 = g_ys[1][bbase + lane];
            v3 = g_ys[1][bbase + lane + 32];
        }
        vals[t * 4 + 0] = v0; vals[t * 4 + 1] = v1;
        vals[t * 4 + 2] = v2; vals[t * 4 + 3] = v3;
        s += v0 + v1 + v2 + v3;
        q += v0 * v0 + v1 * v1 + v2 * v2 + v3 * v3;
    }
    #pragma unroll
    for (int o = 16; o; o >>= 1) { s += __shfl_xor_sync(~0u, s, o); q += __shfl_xor_sync(~0u, q, o); }
    float m = s * (1.f / 640.f);
    float var = q * (1.f / 640.f) - m * m;
    float rs = rsqrtf(var + EPSf);

    float g0 = ln3g[lane],      c0 = ln3b[lane],      w0 = convw[lane];
    float g1 = ln3g[lane + 32], c1 = ln3b[lane + 32], w1 = convw[lane + 32];
    float g2 = ln3g[lane + 64], c2 = ln3b[lane + 64], w2 = convw[lane + 64];
    float g3 = ln3g[lane + 96], c3 = ln3b[lane + 96], w3 = convw[lane + 96];

    float accq = 0.f, msum = 0.f;
    #pragma unroll
    for (int t = 0; t < 5; t++) {
        float p =
            fmaxf((vals[t*4+0] - m) * rs * g0 + c0, 0.f) * w0 +
            fmaxf((vals[t*4+1] - m) * rs * g1 + c1, 0.f) * w1 +
            fmaxf((vals[t*4+2] - m) * rs * g2 + c2, 0.f) * w2 +
            fmaxf((vals[t*4+3] - m) * rs * g3 + c3, 0.f) * w3;
        float mk = mask[(size_t)b * 5 + t];
        accq += p * mk;
        msum += mk;
    }
    #pragma unroll
    for (int o = 16; o; o >>= 1) accq += __shfl_xor_sync(~0u, accq, o);
    if (lane == 0) out[b] = accq + convb[0] * msum;
}

// =====================================================================================
extern "C" void kernel_launch(void* const* d_in, const int* in_sizes, int n_in,
                              void* d_out, int out_size)
{
    (void)in_sizes; (void)n_in; (void)out_size;
    const float* ud     = (const float*)d_in[0];
    const float* action = (const float*)d_in[1];
    const float* mask   = (const float*)d_in[2];
    const float* ln0g   = (const float*)d_in[3];
    const float* ln0b   = (const float*)d_in[4];
    const float* W1     = (const float*)d_in[5];
    const float* b1     = (const float*)d_in[6];
    const float* ln1g   = (const float*)d_in[7];
    const float* ln1b   = (const float*)d_in[8];
    const float* W2     = (const float*)d_in[9];
    const float* b2     = (const float*)d_in[10];
    const float* ln2g   = (const float*)d_in[11];
    const float* ln2b   = (const float*)d_in[12];
    const float* fw_k   = (const float*)d_in[13];
    const float* fw_b   = (const float*)d_in[14];
    const float* bw_k   = (const float*)d_in[15];
    const float* bw_b   = (const float*)d_in[16];
    const float* ln3g   = (const float*)d_in[17];
    const float* ln3b   = (const float*)d_in[18];
    const float* convw  = (const float*)d_in[19];
    const float* convb  = (const float*)d_in[20];
    const int*   au     = (const int*)d_in[21];

    const int MLP_SMEM  = (128*64 + 64*132 + 64*100 + 640 + 64) * 4;   // 94976 B
    const int LSTM_SMEM = (57728 + 256) * 4;                           // 231936 B

    cudaFuncSetAttribute(mlp_kernel,             cudaFuncAttributeMaxDynamicSharedMemorySize, MLP_SMEM);
    cudaFuncSetAttribute(lstm_persistent_kernel, cudaFuncAttributeMaxDynamicSharedMemorySize, LSTM_SMEM);

    zero_cnt_kernel<<<1, 32>>>();
    hist_kernel<<<Bn / 512, 512>>>(au);
    prefix_kernel<<<1, 32>>>();
    scatter_kernel<<<Bn / 512, 512>>>(au);

    mlp_kernel<<<BT / 64, 256, MLP_SMEM>>>(ud, action, ln0g, ln0b, W1, b1,
                                           ln1g, ln1b, W2, b2, ln2g, ln2b);

    lstm_persistent_kernel<<<dim3(Bn / 128, 2), 512, LSTM_SMEM>>>(fw_k, fw_b, bw_k, bw_b, au);

    final_kernel<<<Bn / 8, 256>>>(mask, ln3g, ln3b, convw, convb, au, (float*)d_out);
}

// round 10
// speedup vs baseline: 1.2100x; 1.0457x over previous
#include <cuda_runtime.h>
#include <math.h>

#define Bn   65536
#define Tn   5
#define BT   (Bn*Tn)
#define EPSf 1e-12f

typedef unsigned long long u64;

__device__ float g_x[BT * 64];          // zero-init; invalid (t>=au) slots never written
__device__ float g_ys[2][BT * 64];
__device__ int   g_cnt[5];
__device__ int   g_cursor[5];
__device__ int   g_pbase[5];
__device__ int   g_vbase[6];
__device__ int   g_perm[Bn];

extern __shared__ float smem[];

__device__ __forceinline__ u64 splat2(float x) {
    u64 r; asm("mov.b64 %0, {%1, %1};" : "=l"(r) : "f"(x)); return r;
}
__device__ __forceinline__ void ffma2(u64& d, u64 a, u64 b) {
    asm("fma.rn.f32x2 %0, %1, %2, %0;" : "+l"(d) : "l"(a), "l"(b));
}
__device__ __forceinline__ void lds_v2u64(u64& a, u64& b, unsigned addr) {
    asm volatile("ld.shared.v2.u64 {%0, %1}, [%2];" : "=l"(a), "=l"(b) : "r"(addr));
}
__device__ __forceinline__ float2 unpack2(u64 v) {
    float2 f; asm("mov.b64 {%0, %1}, %2;" : "=f"(f.x), "=f"(f.y) : "l"(v)); return f;
}
__device__ __forceinline__ float sig_f(float x) { return __fdividef(1.f, 1.f + __expf(-x)); }
__device__ __forceinline__ float tanh_f(float x) { return __fdividef(2.f, 1.f + __expf(-2.f * x)) - 1.f; }

#define CP16(dst, src) asm volatile("cp.async.ca.shared.global [%0], [%1], 16;" :: "r"(dst), "l"(src))
#define CP_COMMIT()    asm volatile("cp.async.commit_group;")

// ============================ au counting sort ======================================
__global__ void zero_cnt_kernel() {
    if (threadIdx.x < 5) g_cnt[threadIdx.x] = 0;
}
__global__ __launch_bounds__(512)
void hist_kernel(const int* __restrict__ au) {
    __shared__ int h[5];
    int tid = threadIdx.x;
    if (tid < 5) h[tid] = 0;
    __syncthreads();
    atomicAdd(&h[5 - au[blockIdx.x * 512 + tid]], 1);
    __syncthreads();
    if (tid < 5) atomicAdd(&g_cnt[tid], h[tid]);
}
__global__ void prefix_kernel() {
    if (threadIdx.x == 0) {
        int s = 0, vs = 0;
        #pragma unroll
        for (int i = 0; i < 5; i++) {
            int c = g_cnt[i];
            g_cursor[i] = s;
            g_pbase[i]  = s;
            g_vbase[i]  = vs;
            s  += c;
            vs += c * (5 - i);
        }
        g_vbase[5] = vs;
    }
}
__global__ __launch_bounds__(512)
void scatter_kernel(const int* __restrict__ au) {
    int i = blockIdx.x * 512 + threadIdx.x;
    int lane = threadIdx.x & 31;
    int bkt = 5 - au[i];
    unsigned m = __match_any_sync(0xffffffffu, bkt);
    int leader = __ffs(m) - 1;
    int rank = __popc(m & ((1u << lane) - 1u));
    int base = 0;
    if (lane == leader) base = atomicAdd(&g_cursor[bkt], __popc(m));
    base = __shfl_sync(0xffffffffu, base, leader);
    g_perm[base + rank] = i;
}

// ============================ Kernel 1: fused MLP (R9, proven) ======================
__global__ __launch_bounds__(256)
void mlp_kernel(const float* __restrict__ ud, const float* __restrict__ act,
                const float* __restrict__ ln0g, const float* __restrict__ ln0b,
                const float* __restrict__ W1, const float* __restrict__ b1,
                const float* __restrict__ ln1g, const float* __restrict__ ln1b,
                const float* __restrict__ W2, const float* __restrict__ b2,
                const float* __restrict__ ln2g, const float* __restrict__ ln2b)
{
    const int vtot = g_vbase[5];
    if (blockIdx.x * 64 >= vtot) return;

    float* sW  = smem;
    float* sX  = sW + 128 * 64;
    float* sX2 = sX + 64 * 132;
    float* sP  = sX2 + 64 * 100;
    int*   sRowIdx = (int*)(sP + 640);

    const unsigned sW_a = (unsigned)__cvta_generic_to_shared(sW);
    const int tid = threadIdx.x;

    #pragma unroll
    for (int j = 0; j < 8; j++) {
        int f = tid + j * 256;
        reinterpret_cast<float4*>(sW)[f] = reinterpret_cast<const float4*>(W1)[f];
    }
    if (tid < 128) { sP[tid] = ln0g[tid]; sP[128 + tid] = ln0b[tid]; }
    if (tid < 64) {
        sP[256 + tid] = b1[tid];  sP[320 + tid] = ln1g[tid]; sP[384 + tid] = ln1b[tid];
        sP[448 + tid] = b2[tid];  sP[512 + tid] = ln2g[tid]; sP[576 + tid] = ln2b[tid];
    }

    if (tid < 64) {
        int v = blockIdx.x * 64 + tid;
        int row = -1;
        if (v < vtot) {
            int k = 0;
            #pragma unroll
            for (int j = 1; j < 5; j++) if (v >= g_vbase[j]) k = j;
            int L = 5 - k;
            int idx = v - g_vbase[k];
            int q = idx / L;
            int t = idx - q * L;
            int b = g_perm[g_pbase[k] + q];
            row = b * 5 + t;
        }
        sRowIdx[tid] = row;
    }
    __syncthreads();

    #pragma unroll
    for (int j = 0; j < 8; j++) {
        int f = tid + j * 256;
        int row = f >> 5, c4 = f & 31;
        int gr = sRowIdx[row];
        float4 v = make_float4(0.f, 0.f, 0.f, 0.f);
        if (gr >= 0) v = reinterpret_cast<const float4*>(ud + (size_t)gr * 128)[c4];
        *reinterpret_cast<float4*>(&sX[row * 132 + c4 * 4]) = v;
    }
    #pragma unroll
    for (int j = 0; j < 2; j++) {
        int f = tid + j * 256;
        int row = f >> 3, c4 = f & 7;
        int gr = sRowIdx[row];
        float4 v = make_float4(0.f, 0.f, 0.f, 0.f);
        if (gr >= 0) v = reinterpret_cast<const float4*>(act + (size_t)gr * 32)[c4];
        *reinterpret_cast<float4*>(&sX2[row * 100 + 64 + c4 * 4]) = v;
    }
    __syncthreads();

    const int w = tid >> 5, lane = tid & 31;

    for (int rr = 0; rr < 8; rr++) {
        int row = w * 8 + rr;
        float v0 = sX[row * 132 + lane];
        float v1 = sX[row * 132 + lane + 32];
        float v2 = sX[row * 132 + lane + 64];
        float v3 = sX[row * 132 + lane + 96];
        float s = v0 + v1 + v2 + v3;
        float q = v0 * v0 + v1 * v1 + v2 * v2 + v3 * v3;
        #pragma unroll
        for (int o = 16; o; o >>= 1) { s += __shfl_xor_sync(~0u, s, o); q += __shfl_xor_sync(~0u, q, o); }
        float m = s * (1.f / 128.f);
        float var = q * (1.f / 128.f) - m * m;
        float rs = rsqrtf(var + EPSf);
        sX[row * 132 + lane]      = (v0 - m) * rs * sP[lane]      + sP[128 + lane];
        sX[row * 132 + lane + 32] = (v1 - m) * rs * sP[lane + 32] + sP[128 + lane + 32];
        sX[row * 132 + lane + 64] = (v2 - m) * rs * sP[lane + 64] + sP[128 + lane + 64];
        sX[row * 132 + lane + 96] = (v3 - m) * rs * sP[lane + 96] + sP[128 + lane + 96];
    }
    __syncthreads();

    const int ty = tid >> 4, tx = tid & 15;
    const int ry = ty * 4, cx = tx * 4;

    u64 acc[4][2];
    #pragma unroll
    for (int i = 0; i < 4; i++) { acc[i][0] = 0ull; acc[i][1] = 0ull; }

    for (int k = 0; k < 128; k += 4) {
        float4 a4[4];
        #pragma unroll
        for (int i = 0; i < 4; i++)
            a4[i] = *reinterpret_cast<const float4*>(&sX[(ry + i) * 132 + k]);
        u64 w0[4], w1[4];
        #pragma unroll
        for (int kk = 0; kk < 4; kk++)
            lds_v2u64(w0[kk], w1[kk], sW_a + (unsigned)((k + kk) * 64 + cx) * 4u);
        #pragma unroll
        for (int kk = 0; kk < 4; kk++) {
            #pragma unroll
            for (int i = 0; i < 4; i++) {
                u64 s = splat2((&a4[i].x)[kk]);
                ffma2(acc[i][0], s, w0[kk]);
                ffma2(acc[i][1], s, w1[kk]);
            }
        }
    }
    __syncthreads();

    #pragma unroll
    for (int j = 0; j < 6; j++) {
        int f = tid + j * 256;
        reinterpret_cast<float4*>(sW)[f] = reinterpret_cast<const float4*>(W2)[f];
    }

    {
        float g0 = sP[320 + cx], g1 = sP[320 + cx + 1], g2 = sP[320 + cx + 2], g3 = sP[320 + cx + 3];
        float c0 = sP[384 + cx], c1 = sP[384 + cx + 1], c2 = sP[384 + cx + 2], c3 = sP[384 + cx + 3];
        float b0 = sP[256 + cx], b1v = sP[256 + cx + 1], b2v = sP[256 + cx + 2], b3 = sP[256 + cx + 3];
        #pragma unroll
        for (int i = 0; i < 4; i++) {
            float2 p0 = unpack2(acc[i][0]);
            float2 p1 = unpack2(acc[i][1]);
            float v0 = p0.x + b0, v1 = p0.y + b1v, v2 = p1.x + b2v, v3 = p1.y + b3;
            float s = v0 + v1 + v2 + v3;
            float q = v0 * v0 + v1 * v1 + v2 * v2 + v3 * v3;
            #pragma unroll
            for (int o = 1; o < 16; o <<= 1) { s += __shfl_xor_sync(~0u, s, o); q += __shfl_xor_sync(~0u, q, o); }
            float m = s * (1.f / 64.f);
            float var = q * (1.f / 64.f) - m * m;
            float rs = rsqrtf(var + EPSf);
            float4 o4;
            o4.x = fmaxf((v0 - m) * rs * g0 + c0, 0.f);
            o4.y = fmaxf((v1 - m) * rs * g1 + c1, 0.f);
            o4.z = fmaxf((v2 - m) * rs * g2 + c2, 0.f);
            o4.w = fmaxf((v3 - m) * rs * g3 + c3, 0.f);
            *reinterpret_cast<float4*>(&sX2[(ry + i) * 100 + cx]) = o4;
        }
    }
    __syncthreads();

    u64 acc2[4][2];
    #pragma unroll
    for (int i = 0; i < 4; i++) { acc2[i][0] = 0ull; acc2[i][1] = 0ull; }

    for (int k = 0; k < 96; k += 4) {
        float4 a4[4];
        #pragma unroll
        for (int i = 0; i < 4; i++)
            a4[i] = *reinterpret_cast<const float4*>(&sX2[(ry + i) * 100 + k]);
        u64 w0[4], w1[4];
        #pragma unroll
        for (int kk = 0; kk < 4; kk++)
            lds_v2u64(w0[kk], w1[kk], sW_a + (unsigned)((k + kk) * 64 + cx) * 4u);
        #pragma unroll
        for (int kk = 0; kk < 4; kk++) {
            #pragma unroll
            for (int i = 0; i < 4; i++) {
                u64 s = splat2((&a4[i].x)[kk]);
                ffma2(acc2[i][0], s, w0[kk]);
                ffma2(acc2[i][1], s, w1[kk]);
            }
        }
    }

    {
        float g0 = sP[512 + cx], g1 = sP[512 + cx + 1], g2 = sP[512 + cx + 2], g3 = sP[512 + cx + 3];
        float c0 = sP[576 + cx], c1 = sP[576 + cx + 1], c2 = sP[576 + cx + 2], c3 = sP[576 + cx + 3];
        float b0 = sP[448 + cx], b1v = sP[448 + cx + 1], b2v = sP[448 + cx + 2], b3 = sP[448 + cx + 3];
        #pragma unroll
        for (int i = 0; i < 4; i++) {
            float2 p0 = unpack2(acc2[i][0]);
            float2 p1 = unpack2(acc2[i][1]);
            float v0 = p0.x + b0, v1 = p0.y + b1v, v2 = p1.x + b2v, v3 = p1.y + b3;
            float s = v0 + v1 + v2 + v3;
            float q = v0 * v0 + v1 * v1 + v2 * v2 + v3 * v3;
            #pragma unroll
            for (int o = 1; o < 16; o <<= 1) { s += __shfl_xor_sync(~0u, s, o); q += __shfl_xor_sync(~0u, q, o); }
            float m = s * (1.f / 64.f);
            float var = q * (1.f / 64.f) - m * m;
            float rs = rsqrtf(var + EPSf);
            int gr = sRowIdx[ry + i];
            if (gr >= 0) {
                float4 o4;
                o4.x = fmaxf((v0 - m) * rs * g0 + c0, 0.f);
                o4.y = fmaxf((v1 - m) * rs * g1 + c1, 0.f);
                o4.z = fmaxf((v2 - m) * rs * g2 + c2, 0.f);
                o4.w = fmaxf((v3 - m) * rs * g3 + c3, 0.f);
                *reinterpret_cast<float4*>(&g_x[(size_t)gr * 64 + cx]) = o4;
            }
        }
    }
}

// ===================== Kernel 2: persistent LSTM, row-pair-packed GEMM ==============
// Warp = 8 hcol-lanes x 4 row-lanes. Weight LDS.128 moves 128 B (4-way broadcast);
// A comes pre-packed (row pairs) from transposed tiles xT / sHT. FMA-bound by design.
// sKp[k*256 + hp*8 + g*2 + e] = K[k][g*64 + hp*2 + e]
#define LSTM_K(wk, A_a, astr, ak) do {                                                   \
    float4 wij = *reinterpret_cast<const float4*>(sKp + (wk) * 256 + hp * 8);            \
    float4 wfo = *reinterpret_cast<const float4*>(sKp + (wk) * 256 + hp * 8 + 4);        \
    u64 a01, a23, a45, a67;                                                              \
    lds_v2u64(a01, a23, (A_a) + (unsigned)((ak) * (astr) + r0) * 4u);                    \
    lds_v2u64(a45, a67, (A_a) + (unsigned)((ak) * (astr) + r0 + 4) * 4u);                \
    u64 s_;                                                                              \
    s_ = splat2(wij.x); ffma2(acc[0][0][0],s_,a01); ffma2(acc[0][0][1],s_,a23);          \
                        ffma2(acc[0][0][2],s_,a45); ffma2(acc[0][0][3],s_,a67);          \
    s_ = splat2(wij.y); ffma2(acc[0][1][0],s_,a01); ffma2(acc[0][1][1],s_,a23);          \
                        ffma2(acc[0][1][2],s_,a45); ffma2(acc[0][1][3],s_,a67);          \
    s_ = splat2(wij.z); ffma2(acc[1][0][0],s_,a01); ffma2(acc[1][0][1],s_,a23);          \
                        ffma2(acc[1][0][2],s_,a45); ffma2(acc[1][0][3],s_,a67);          \
    s_ = splat2(wij.w); ffma2(acc[1][1][0],s_,a01); ffma2(acc[1][1][1],s_,a23);          \
                        ffma2(acc[1][1][2],s_,a45); ffma2(acc[1][1][3],s_,a67);          \
    s_ = splat2(wfo.x); ffma2(acc[2][0][0],s_,a01); ffma2(acc[2][0][1],s_,a23);          \
                        ffma2(acc[2][0][2],s_,a45); ffma2(acc[2][0][3],s_,a67);          \
    s_ = splat2(wfo.y); ffma2(acc[2][1][0],s_,a01); ffma2(acc[2][1][1],s_,a23);          \
                        ffma2(acc[2][1][2],s_,a45); ffma2(acc[2][1][3],s_,a67);          \
    s_ = splat2(wfo.z); ffma2(acc[3][0][0],s_,a01); ffma2(acc[3][0][1],s_,a23);          \
                        ffma2(acc[3][0][2],s_,a45); ffma2(acc[3][0][3],s_,a67);          \
    s_ = splat2(wfo.w); ffma2(acc[3][1][0],s_,a01); ffma2(acc[3][1][1],s_,a23);          \
                        ffma2(acc[3][1][2],s_,a45); ffma2(acc[3][1][3],s_,a67);          \
} while (0)

__global__ __launch_bounds__(512, 1)
void lstm_persistent_kernel(const float* __restrict__ fw_k, const float* __restrict__ fw_b,
                            const float* __restrict__ bw_k, const float* __restrict__ bw_b,
                            const int* __restrict__ au)
{
    float* sKp   = smem;                   // 32768: permuted weights
    float* stage = smem + 32768;           // 8192: raw x tile [128][64]
    float* xT    = smem + 40960;           // 8192: [64 k][128 rows]
    float* sHT   = smem + 49152;           // 8448: [64 hc][132] transposed h
    int*   sAu   = (int*)(smem + 57600);   // 128
    int*   sPb   = sAu + 128;              // 128

    const unsigned xT_a  = (unsigned)__cvta_generic_to_shared(xT);
    const unsigned sHT_a = (unsigned)__cvta_generic_to_shared(sHT);

    const int dir = blockIdx.y;
    const float* K    = dir ? bw_k : fw_k;
    const float* bias = dir ? bw_b : fw_b;
    float* gy = g_ys[dir];

    const int b0   = blockIdx.x * 128;
    const int tid  = threadIdx.x;
    const int lane = tid & 31, w = tid >> 5;
    const int hsub = lane & 7, rsub = lane >> 3;
    const int wcol = w & 3,  wrow = w >> 2;
    const int hp   = wcol * 8 + hsub;       // hcol-pair index (0..31)
    const int hx   = hp * 2;
    const int r0   = (wrow * 4 + rsub) * 8; // 8 rows per thread

    const int mx = au[g_perm[b0]];

    // ---- prefetch x_0 into stage (single buffer; transpose frees it) ----
    {
        int row = tid >> 2, seg = tid & 3;
        int pb = g_perm[b0 + row];
        int a = au[pb];
        int ts = dir ? (a - 1) : 0;         // t=0 always valid (a >= 1)
        const float* src = g_x + ((size_t)pb * 5 + ts) * 64 + seg * 16;
        unsigned dst = (unsigned)__cvta_generic_to_shared(stage + row * 64 + seg * 16);
        #pragma unroll
        for (int q = 0; q < 4; q++) CP16(dst + q * 16, src + q * 4);
        CP_COMMIT();
        if (seg == 0) { sAu[row] = a; sPb[row] = pb; }
    }

    // ---- load + permute K ----
    #pragma unroll
    for (int it = 0; it < 16; it++) {
        int f = tid + it * 512;
        int kk = f >> 6, c4 = f & 63;
        float4 v = reinterpret_cast<const float4*>(K + (size_t)kk * 256)[c4];
        int g   = c4 >> 4;
        int hp0 = (c4 & 15) * 2;
        *reinterpret_cast<float2*>(&sKp[kk * 256 + hp0 * 8 + g * 2])       = make_float2(v.x, v.y);
        *reinterpret_cast<float2*>(&sKp[kk * 256 + (hp0 + 1) * 8 + g * 2]) = make_float2(v.z, v.w);
    }

    float2 bg[4];
    #pragma unroll
    for (int g = 0; g < 4; g++)
        bg[g] = *reinterpret_cast<const float2*>(bias + g * 64 + hx);

    float2 cc[8];   // cell state: 8 rows x 2 cols
    #pragma unroll
    for (int i = 0; i < 8; i++) cc[i] = make_float2(0.f, 0.f);

    for (int t = 0; t < mx; t++) {
        asm volatile("cp.async.wait_group 0;" ::: "memory");
        __syncthreads();   // stage(x_t) ready; sHT(t-1) published; xT free

        // ---- transpose stage -> xT ----
        {
            int row = tid >> 2, kc = (tid & 3) * 16;
            #pragma unroll
            for (int q = 0; q < 4; q++) {
                float4 v = *reinterpret_cast<const float4*>(&stage[row * 64 + kc + q * 4]);
                xT[(kc + q * 4 + 0) * 128 + row] = v.x;
                xT[(kc + q * 4 + 1) * 128 + row] = v.y;
                xT[(kc + q * 4 + 2) * 128 + row] = v.z;
                xT[(kc + q * 4 + 3) * 128 + row] = v.w;
            }
        }
        __syncthreads();   // xT ready; stage free

        // ---- prefetch x_{t+1} (overlaps GEMM) ----
        if (t + 1 < mx) {
            int row = tid >> 2, seg = tid & 3;
            int pb = sPb[row];
            int a = sAu[row];
            int tt = t + 1;
            int ts = dir ? ((tt < a) ? (a - 1 - tt) : tt) : tt;
            const float* src = g_x + ((size_t)pb * 5 + ts) * 64 + seg * 16;
            unsigned dst = (unsigned)__cvta_generic_to_shared(stage + row * 64 + seg * 16);
            #pragma unroll
            for (int q = 0; q < 4; q++) CP16(dst + q * 16, src + q * 4);
            CP_COMMIT();
        } else {
            CP_COMMIT();   // keep group count consistent for loop-top wait
        }

        // ---- GEMM ----
        u64 acc[4][2][4];   // [gate][col][rowpair]
        #pragma unroll
        for (int g = 0; g < 4; g++)
            #pragma unroll
            for (int e = 0; e < 2; e++)
                #pragma unroll
                for (int rp = 0; rp < 4; rp++) acc[g][e][rp] = 0ull;

        #pragma unroll 2
        for (int k = 0; k < 64; k++) LSTM_K(k, xT_a, 128, k);

        if (t > 0) {
            #pragma unroll 2
            for (int k = 0; k < 64; k++) LSTM_K(k + 64, sHT_a, 132, k);
        }

        __syncthreads();   // GEMM reads of sHT done before epilogue rewrites it

        // ---- epilogue: 8 rows x 2 cols per thread ----
        float h0[8], h1[8];
        if (t > 0) {
            float4 p = *reinterpret_cast<const float4*>(&sHT[hx * 132 + r0]);
            float4 q = *reinterpret_cast<const float4*>(&sHT[hx * 132 + r0 + 4]);
            h0[0]=p.x; h0[1]=p.y; h0[2]=p.z; h0[3]=p.w;
            h0[4]=q.x; h0[5]=q.y; h0[6]=q.z; h0[7]=q.w;
            p = *reinterpret_cast<const float4*>(&sHT[(hx + 1) * 132 + r0]);
            q = *reinterpret_cast<const float4*>(&sHT[(hx + 1) * 132 + r0 + 4]);
            h1[0]=p.x; h1[1]=p.y; h1[2]=p.z; h1[3]=p.w;
            h1[4]=q.x; h1[5]=q.y; h1[6]=q.z; h1[7]=q.w;
        } else {
            #pragma unroll
            for (int i = 0; i < 8; i++) { h0[i] = 0.f; h1[i] = 0.f; }
        }

        float hn0[8], hn1[8];
        #pragma unroll
        for (int rp = 0; rp < 4; rp++) {
            float2 vi0 = unpack2(acc[0][0][rp]), vi1 = unpack2(acc[0][1][rp]);
            float2 vj0 = unpack2(acc[1][0][rp]), vj1 = unpack2(acc[1][1][rp]);
            float2 vf0 = unpack2(acc[2][0][rp]), vf1 = unpack2(acc[2][1][rp]);
            float2 vo0 = unpack2(acc[3][0][rp]), vo1 = unpack2(acc[3][1][rp]);
            #pragma unroll
            for (int h2 = 0; h2 < 2; h2++) {
                int i = rp * 2 + h2;
                int row = r0 + i;
                bool valid = (t < sAu[row]);
                float gi0 = (h2 ? vi0.y : vi0.x) + bg[0].x;
                float gi1 = (h2 ? vi1.y : vi1.x) + bg[0].y;
                float gj0 = (h2 ? vj0.y : vj0.x) + bg[1].x;
                float gj1 = (h2 ? vj1.y : vj1.x) + bg[1].y;
                float gf0 = (h2 ? vf0.y : vf0.x) + bg[2].x;
                float gf1 = (h2 ? vf1.y : vf1.x) + bg[2].y;
                float go0 = (h2 ? vo0.y : vo0.x) + bg[3].x;
                float go1 = (h2 ? vo1.y : vo1.x) + bg[3].y;

                float c0o = cc[i].x, c1o = cc[i].y;
                float cn0 = sig_f(gf0 + 1.f) * c0o + sig_f(gi0) * tanh_f(gj0);
                float cn1 = sig_f(gf1 + 1.f) * c1o + sig_f(gi1) * tanh_f(gj1);
                float hh0 = sig_f(go0) * tanh_f(cn0);
                float hh1 = sig_f(go1) * tanh_f(cn1);

                cc[i].x = valid ? cn0 : c0o;
                cc[i].y = valid ? cn1 : c1o;
                hn0[i] = valid ? hh0 : h0[i];
                hn1[i] = valid ? hh1 : h1[i];

                float2 yw = make_float2(valid ? hh0 : 0.f, valid ? hh1 : 0.f);
                *reinterpret_cast<float2*>(gy + ((size_t)sPb[row] * 5 + t) * 64 + hx) = yw;
            }
        }

        // store h transposed for next step's GEMM
        *reinterpret_cast<float4*>(&sHT[hx * 132 + r0])           = make_float4(hn0[0], hn0[1], hn0[2], hn0[3]);
        *reinterpret_cast<float4*>(&sHT[hx * 132 + r0 + 4])       = make_float4(hn0[4], hn0[5], hn0[6], hn0[7]);
        *reinterpret_cast<float4*>(&sHT[(hx + 1) * 132 + r0])     = make_float4(hn1[0], hn1[1], hn1[2], hn1[3]);
        *reinterpret_cast<float4*>(&sHT[(hx + 1) * 132 + r0 + 4]) = make_float4(hn1[4], hn1[5], hn1[6], hn1[7]);
        // loop-top __syncthreads() publishes sHT before next GEMM
    }
    asm volatile("cp.async.wait_group 0;" ::: "memory");
}

// ============================ Kernel 3: final =======================================
__global__ __launch_bounds__(256)
void final_kernel(const float* __restrict__ mask,
                  const float* __restrict__ ln3g, const float* __restrict__ ln3b,
                  const float* __restrict__ convw, const float* __restrict__ convb,
                  const int* __restrict__ au, float* __restrict__ out)
{
    int b = blockIdx.x * 8 + (threadIdx.x >> 5);
    int lane = threadIdx.x & 31;
    int a = au[b];

    float vals[20];
    float s = 0.f, q = 0.f;
    #pragma unroll
    for (int t = 0; t < 5; t++) {
        float v0 = 0.f, v1 = 0.f, v2 = 0.f, v3 = 0.f;
        if (t < a) {
            int rt = a - 1 - t;
            size_t fbase = ((size_t)b * 5 + t)  * 64;
            size_t bbase = ((size_t)b * 5 + rt) * 64;
            v0 = g_ys[0][fbase + lane];
            v1 = g_ys[0][fbase + lane + 32];
            v2 = g_ys[1][bbase + lane];
            v3 = g_ys[1][bbase + lane + 32];
        }
        vals[t * 4 + 0] = v0; vals[t * 4 + 1] = v1;
        vals[t * 4 + 2] = v2; vals[t * 4 + 3] = v3;
        s += v0 + v1 + v2 + v3;
        q += v0 * v0 + v1 * v1 + v2 * v2 + v3 * v3;
    }
    #pragma unroll
    for (int o = 16; o; o >>= 1) { s += __shfl_xor_sync(~0u, s, o); q += __shfl_xor_sync(~0u, q, o); }
    float m = s * (1.f / 640.f);
    float var = q * (1.f / 640.f) - m * m;
    float rs = rsqrtf(var + EPSf);

    float g0 = ln3g[lane],      c0 = ln3b[lane],      w0 = convw[lane];
    float g1 = ln3g[lane + 32], c1 = ln3b[lane + 32], w1 = convw[lane + 32];
    float g2 = ln3g[lane + 64], c2 = ln3b[lane + 64], w2 = convw[lane + 64];
    float g3 = ln3g[lane + 96], c3 = ln3b[lane + 96], w3 = convw[lane + 96];

    float accq = 0.f, msum = 0.f;
    #pragma unroll
    for (int t = 0; t < 5; t++) {
        float p =
            fmaxf((vals[t*4+0] - m) * rs * g0 + c0, 0.f) * w0 +
            fmaxf((vals[t*4+1] - m) * rs * g1 + c1, 0.f) * w1 +
            fmaxf((vals[t*4+2] - m) * rs * g2 + c2, 0.f) * w2 +
            fmaxf((vals[t*4+3] - m) * rs * g3 + c3, 0.f) * w3;
        float mk = mask[(size_t)b * 5 + t];
        accq += p * mk;
        msum += mk;
    }
    #pragma unroll
    for (int o = 16; o; o >>= 1) accq += __shfl_xor_sync(~0u, accq, o);
    if (lane == 0) out[b] = accq + convb[0] * msum;
}

// =====================================================================================
extern "C" void kernel_launch(void* const* d_in, const int* in_sizes, int n_in,
                              void* d_out, int out_size)
{
    (void)in_sizes; (void)n_in; (void)out_size;
    const float* ud     = (const float*)d_in[0];
    const float* action = (const float*)d_in[1];
    const float* mask   = (const float*)d_in[2];
    const float* ln0g   = (const float*)d_in[3];
    const float* ln0b   = (const float*)d_in[4];
    const float* W1     = (const float*)d_in[5];
    const float* b1     = (const float*)d_in[6];
    const float* ln1g   = (const float*)d_in[7];
    const float* ln1b   = (const float*)d_in[8];
    const float* W2     = (const float*)d_in[9];
    const float* b2     = (const float*)d_in[10];
    const float* ln2g   = (const float*)d_in[11];
    const float* ln2b   = (const float*)d_in[12];
    const float* fw_k   = (const float*)d_in[13];
    const float* fw_b   = (const float*)d_in[14];
    const float* bw_k   = (const float*)d_in[15];
    const float* bw_b   = (const float*)d_in[16];
    const float* ln3g   = (const float*)d_in[17];
    const float* ln3b   = (const float*)d_in[18];
    const float* convw  = (const float*)d_in[19];
    const float* convb  = (const float*)d_in[20];
    const int*   au     = (const int*)d_in[21];

    const int MLP_SMEM  = (128*64 + 64*132 + 64*100 + 640 + 64) * 4;   // 94976 B
    const int LSTM_SMEM = (32768 + 8192 + 8192 + 8448 + 256) * 4;      // 231424 B

    cudaFuncSetAttribute(mlp_kernel,             cudaFuncAttributeMaxDynamicSharedMemorySize, MLP_SMEM);
    cudaFuncSetAttribute(lstm_persistent_kernel, cudaFuncAttributeMaxDynamicSharedMemorySize, LSTM_SMEM);

    zero_cnt_kernel<<<1, 32>>>();
    hist_kernel<<<Bn / 512, 512>>>(au);
    prefix_kernel<<<1, 32>>>();
    scatter_kernel<<<Bn / 512, 512>>>(au);

    mlp_kernel<<<BT / 64, 256, MLP_SMEM>>>(ud, action, ln0g, ln0b, W1, b1,
                                           ln1g, ln1b, W2, b2, ln2g, ln2b);

    lstm_persistent_kernel<<<dim3(Bn / 128, 2), 512, LSTM_SMEM>>>(fw_k, fw_b, bw_k, bw_b, au);

    final_kernel<<<Bn / 8, 256>>>(mask, ln3g, ln3b, convw, convb, au, (float*)d_out);
}